// round 5
// baseline (speedup 1.0000x reference)
#include <cuda_runtime.h>

// LIF forward: X[B=128, T=32, N=8192] fp32 -> spikes fp32.
// R5: single-wave residency. R1 layout (1 float4 column per thread, full-T
// unrolled recurrence) with __launch_bounds__(256, 7) so regs <= 36 and all
// 1024 CTAs fit in one wave (7 CTAs/SM x 148 SMs = 1036 >= 1024). This
// removes the 2-wave quantization (1024/740 = 1.38 waves) that capped DRAM
// at ~70% in R1-R4.

static constexpr int B = 128;
static constexpr int T = 32;
static constexpr int N = 8192;
static constexpr int N4 = N / 4;          // 2048 float4 columns
static constexpr int TOTAL4 = B * N4;     // 262144 float4 lanes
static constexpr int TPB = 256;

__device__ __forceinline__ float4 step4(float4& m, const float4 x) {
    m.x = m.x + (x.x - m.x) * 0.5f;
    m.y = m.y + (x.y - m.y) * 0.5f;
    m.z = m.z + (x.z - m.z) * 0.5f;
    m.w = m.w + (x.w - m.w) * 0.5f;
    float4 s;
    s.x = (m.x > 1.0f) ? 1.0f : 0.0f;
    s.y = (m.y > 1.0f) ? 1.0f : 0.0f;
    s.z = (m.z > 1.0f) ? 1.0f : 0.0f;
    s.w = (m.w > 1.0f) ? 1.0f : 0.0f;
    if (s.x != 0.0f) m.x = 0.0f;
    if (s.y != 0.0f) m.y = 0.0f;
    if (s.z != 0.0f) m.z = 0.0f;
    if (s.w != 0.0f) m.w = 0.0f;
    return s;
}

__global__ __launch_bounds__(TPB, 7) void lif_kernel(const float4* __restrict__ X,
                                                     float4* __restrict__ out) {
    int idx = blockIdx.x * TPB + threadIdx.x;  // 0 .. TOTAL4-1

    int b = idx / N4;
    int n4 = idx - b * N4;

    const float4* xp = X + (size_t)b * T * N4 + n4;
    float4* op = out + (size_t)b * T * N4 + n4;

    float4 m = make_float4(0.f, 0.f, 0.f, 0.f);

#pragma unroll
    for (int t = 0; t < T; t++) {
        float4 x = xp[(size_t)t * N4];
        float4 s = step4(m, x);
        op[(size_t)t * N4] = s;
    }
}

extern "C" void kernel_launch(void* const* d_in, const int* in_sizes, int n_in,
                              void* d_out, int out_size) {
    const float4* X = (const float4*)d_in[0];
    float4* out = (float4*)d_out;
    lif_kernel<<<TOTAL4 / TPB, TPB>>>(X, out);
}

// round 6
// speedup vs baseline: 1.0441x; 1.0441x over previous
#include <cuda_runtime.h>

// LIF forward: X[B=128, T=32, N=8192] fp32 -> spikes fp32.
// R6: R5 skeleton (1 float4 column/thread, full-T unroll, maxblocks=7 so
// regs<=32 and single-wave residency) + streaming cache ops isolated as the
// single change: __ldcs on the input stream, __stcs on the spike stream.
// Both streams are touch-once; evict-first keeps L2 from allocate/evict
// churn against the 7.0 TB/s effective HBM stream (88% of spec — near the
// mixed read/write ceiling).

static constexpr int B = 128;
static constexpr int T = 32;
static constexpr int N = 8192;
static constexpr int N4 = N / 4;          // 2048 float4 columns
static constexpr int TOTAL4 = B * N4;     // 262144 float4 lanes
static constexpr int TPB = 256;

__device__ __forceinline__ float4 step4(float4& m, const float4 x) {
    m.x = m.x + (x.x - m.x) * 0.5f;
    m.y = m.y + (x.y - m.y) * 0.5f;
    m.z = m.z + (x.z - m.z) * 0.5f;
    m.w = m.w + (x.w - m.w) * 0.5f;
    float4 s;
    s.x = (m.x > 1.0f) ? 1.0f : 0.0f;
    s.y = (m.y > 1.0f) ? 1.0f : 0.0f;
    s.z = (m.z > 1.0f) ? 1.0f : 0.0f;
    s.w = (m.w > 1.0f) ? 1.0f : 0.0f;
    if (s.x != 0.0f) m.x = 0.0f;
    if (s.y != 0.0f) m.y = 0.0f;
    if (s.z != 0.0f) m.z = 0.0f;
    if (s.w != 0.0f) m.w = 0.0f;
    return s;
}

__global__ __launch_bounds__(TPB, 7) void lif_kernel(const float4* __restrict__ X,
                                                     float4* __restrict__ out) {
    int idx = blockIdx.x * TPB + threadIdx.x;  // 0 .. TOTAL4-1

    int b = idx / N4;
    int n4 = idx - b * N4;

    const float4* xp = X + (size_t)b * T * N4 + n4;
    float4* op = out + (size_t)b * T * N4 + n4;

    float4 m = make_float4(0.f, 0.f, 0.f, 0.f);

#pragma unroll
    for (int t = 0; t < T; t++) {
        float4 x = __ldcs(&xp[(size_t)t * N4]);
        float4 s = step4(m, x);
        __stcs(&op[(size_t)t * N4], s);
    }
}

extern "C" void kernel_launch(void* const* d_in, const int* in_sizes, int n_in,
                              void* d_out, int out_size) {
    const float4* X = (const float4*)d_in[0];
    float4* out = (float4*)d_out;
    lif_kernel<<<TOTAL4 / TPB, TPB>>>(X, out);
}